// round 14
// baseline (speedup 1.0000x reference)
#include <cuda_runtime.h>
#include <math.h>
#include <cstdint>

#define B_   128
#define T_   512
#define D_   256
#define H_   512
#define G4_  2048   // 4*H

// ---- static device scratch (no cudaMalloc allowed) ----
__device__ float g_xp[(size_t)T_ * B_ * G4_];   // [T*B, 4H] x-projections (+biases)
__device__ float g_h[2][B_ * H_];               // ping-pong hidden state (tf32-rounded)
__device__ unsigned g_cntB[128];                // 4 bt-group barrier counters, 128B apart
__device__ volatile unsigned g_genB[128];       // 4 bt-group barrier generations

// =====================================================================
// helpers
// =====================================================================
__device__ __forceinline__ float tf32r(float x) {
    float y; asm("cvt.rna.tf32.f32 %0, %1;" : "=f"(y) : "f"(x)); return y;
}
__device__ __forceinline__ uint32_t smem_u32(const void* p) {
    uint32_t a;
    asm("{ .reg .u64 t; cvta.to.shared.u64 t, %1; cvt.u32.u64 %0, t; }" : "=r"(a) : "l"(p));
    return a;
}
// ldmatrix x4: four 8x8 b16 tiles == one 16x8 tf32 A-frag or two 8x8 tf32 B-frags
__device__ __forceinline__ void ldsm4(uint32_t* r, uint32_t addr) {
    asm volatile("ldmatrix.sync.aligned.m8n8.x4.shared.b16 {%0,%1,%2,%3}, [%4];"
                 : "=r"(r[0]), "=r"(r[1]), "=r"(r[2]), "=r"(r[3]) : "r"(addr));
}
// ldmatrix x2: two 8x8 b16 tiles == one 8x8 tf32 B-frag (k, k+4)
__device__ __forceinline__ void ldsm2(uint32_t* r, uint32_t addr) {
    asm volatile("ldmatrix.sync.aligned.m8n8.x2.shared.b16 {%0,%1}, [%2];"
                 : "=r"(r[0]), "=r"(r[1]) : "r"(addr));
}
// mma.sync m16n8k8 tf32, fp32 accum
__device__ __forceinline__ void mma1688(float* c, const uint32_t* a, const uint32_t* b) {
    asm volatile(
        "mma.sync.aligned.m16n8k8.row.col.f32.tf32.tf32.f32 "
        "{%0,%1,%2,%3}, {%4,%5,%6,%7}, {%8,%9}, {%0,%1,%2,%3};"
        : "+f"(c[0]), "+f"(c[1]), "+f"(c[2]), "+f"(c[3])
        : "r"(a[0]), "r"(a[1]), "r"(a[2]), "r"(a[3]), "r"(b[0]), "r"(b[1]));
}
// 32-CTA bt-group barrier
__device__ __forceinline__ void grid_barrier_bt(int step, int bt)
{
    __syncthreads();
    if (threadIdx.x == 0) {
        unsigned next = (unsigned)((step + 1) & (T_ - 1));
        __threadfence();
        unsigned old = atomicAdd(&g_cntB[bt * 32], 1u);
        if (old == 31u) {
            g_cntB[bt * 32] = 0;
            __threadfence();
            g_genB[bt * 32] = next;
        } else {
            while (g_genB[bt * 32] != next) { }
        }
        __threadfence();
    }
    __syncthreads();
}

// =====================================================================
// Kernel 1: x_proj GEMM via tf32 mma + ldmatrix (round-13 exact)
// =====================================================================
#define XA_STR 68
#define XB_STR 68
#define XP_SMEM ((128 * XA_STR + 64 * XB_STR) * 4)

__global__ void __launch_bounds__(256, 1) xproj_mma(
    const float* __restrict__ x,     // [B*T, D]
    const float* __restrict__ Wih,   // [4H, D]
    const float* __restrict__ bih,
    const float* __restrict__ bhh)
{
    extern __shared__ float sm[];
    float* Ash = sm;                   // [128][68]
    float* Bsh = sm + 128 * XA_STR;    // [64][68]
    const uint32_t sb = smem_u32(sm);

    const int tid  = threadIdx.x;
    const int wid  = tid >> 5;
    const int lane = tid & 31;
    const int g    = lane >> 2;
    const int tig  = lane & 3;
    const int wm   = wid & 3;
    const int wcol = (wid >> 2) * 32;

    const int mt = blockIdx.x >> 5;
    const int nt = blockIdx.x & 31;
    const int m0 = mt * 128;
    const int n0 = nt * 64;

    const uint32_t aAddr1 = sb + (uint32_t)((wm * 32 + (lane & 15)) * XA_STR + ((lane >> 4) << 2)) * 4;
    const uint32_t aAddr2 = aAddr1 + (uint32_t)(16 * XA_STR) * 4;
    const uint32_t bBase  = sb + (uint32_t)(128 * XA_STR) * 4;
    const uint32_t bAddr1 = bBase + (uint32_t)((wcol + (lane & 7) + ((lane >> 4) << 3)) * XB_STR
                                               + (((lane >> 3) & 1) << 2)) * 4;
    const uint32_t bAddr2 = bAddr1 + (uint32_t)(16 * XB_STR) * 4;

    float c[2][4][4];
#pragma unroll
    for (int a = 0; a < 2; ++a)
#pragma unroll
        for (int b = 0; b < 4; ++b)
#pragma unroll
            for (int i = 0; i < 4; ++i) c[a][b][i] = 0.f;

    for (int kc = 0; kc < 4; ++kc) {
        const int k0 = kc * 64;
        __syncthreads();
        {
            int row = tid >> 1;
            int h   = (tid & 1) * 32;
            const float* src = x + (size_t)(m0 + row) * D_ + k0 + h;
            float* dst = Ash + row * XA_STR + h;
#pragma unroll
            for (int i = 0; i < 8; ++i) {
                float4 v = *(const float4*)(src + i * 4);
                v.x = tf32r(v.x); v.y = tf32r(v.y); v.z = tf32r(v.z); v.w = tf32r(v.w);
                *(float4*)(dst + i * 4) = v;
            }
        }
        {
            int n = tid >> 2;
            int h = (tid & 3) * 16;
            const float* src = Wih + (size_t)(n0 + n) * D_ + k0 + h;
            float* dst = Bsh + n * XB_STR + h;
#pragma unroll
            for (int i = 0; i < 4; ++i) {
                float4 v = *(const float4*)(src + i * 4);
                v.x = tf32r(v.x); v.y = tf32r(v.y); v.z = tf32r(v.z); v.w = tf32r(v.w);
                *(float4*)(dst + i * 4) = v;
            }
        }
        __syncthreads();

#pragma unroll 4
        for (int kk = 0; kk < 8; ++kk) {
            const uint32_t koff = (uint32_t)kk * 32;
            uint32_t af0[4], af1[4], bb01[4], bb23[4];
            ldsm4(af0,  aAddr1 + koff);
            ldsm4(af1,  aAddr2 + koff);
            ldsm4(bb01, bAddr1 + koff);
            ldsm4(bb23, bAddr2 + koff);
            mma1688(c[0][0], af0, bb01); mma1688(c[0][1], af0, bb01 + 2);
            mma1688(c[0][2], af0, bb23); mma1688(c[0][3], af0, bb23 + 2);
            mma1688(c[1][0], af1, bb01); mma1688(c[1][1], af1, bb01 + 2);
            mma1688(c[1][2], af1, bb23); mma1688(c[1][3], af1, bb23 + 2);
        }
    }

    float2 bias[4];
#pragma unroll
    for (int nf = 0; nf < 4; ++nf) {
        int col = n0 + wcol + nf * 8 + 2 * tig;
        bias[nf].x = bih[col] + bhh[col];
        bias[nf].y = bih[col + 1] + bhh[col + 1];
    }
#pragma unroll
    for (int mf = 0; mf < 2; ++mf) {
#pragma unroll
        for (int rs = 0; rs < 2; ++rs) {
            int grow = m0 + wm * 32 + mf * 16 + g + rs * 8;
            int b = grow >> 9;
            int t = grow & 511;
            float* orow = g_xp + ((size_t)t * B_ + b) * G4_ + n0 + wcol + 2 * tig;
#pragma unroll
            for (int nf = 0; nf < 4; ++nf) {
                float2 v;
                v.x = c[mf][nf][rs * 2 + 0] + bias[nf].x;
                v.y = c[mf][nf][rs * 2 + 1] + bias[nf].y;
                *(float2*)(orow + nf * 8) = v;
            }
        }
    }
}

// =====================================================================
// Kernel 2: persistent tf32 mma recurrence.
//   Round-12 skeleton; ALL 8 warps now compute: warp w -> gate q=w>>1,
//   N-half h=w&1 (cols q*16+h*8 .. +8). 2 compute warps per SMSP hide
//   the ldsm->mma chain latency. Staging/cell/barrier unchanged.
// =====================================================================
#define W_STR 516           // Wsh/Hsh row stride (floats), pad 4
#define G_STR 68
#define REC_SMEM ((64 * W_STR + 32 * W_STR + 32 * G_STR) * 4)

__global__ void __launch_bounds__(256, 1) lstm_rec_mma(
    const float* __restrict__ Whh,   // [4H, H]
    float* __restrict__ out)         // [T*B, H]
{
    extern __shared__ float sm[];
    float* Wsh = sm;                     // [64 n][516]
    float* Hsh = sm + 64 * W_STR;        // [32 b][516]
    float* Gsh = Hsh + 32 * W_STR;       // [32 b][68]
    const uint32_t sb = smem_u32(sm);

    const int tid  = threadIdx.x;
    const int wid  = tid >> 5;
    const int lane = tid & 31;
    const int g    = lane >> 2;
    const int tig  = lane & 3;

    const int bt = blockIdx.x >> 5;
    const int jt = blockIdx.x & 31;
    const int b0 = bt * 32;
    const int j0 = jt * 16;

    // ---- one-time: W_hh slice [64 n][512 k] -> SMEM (tf32-rna) ----
    {
        int n  = tid >> 2;               // 0..63 : n = q*16 + jl
        int kq = (tid & 3) * 128;
        int q  = n >> 4, jl = n & 15;
        const float* wr = Whh + (size_t)(q * H_ + j0 + jl) * H_ + kq;
        float* dst = Wsh + n * W_STR + kq;
#pragma unroll 8
        for (int i = 0; i < 128; i += 4) {
            float4 v = *(const float4*)(wr + i);
            v.x = tf32r(v.x); v.y = tf32r(v.y); v.z = tf32r(v.z); v.w = tf32r(v.w);
            *(float4*)(dst + i) = v;
        }
    }
    __syncthreads();

    // compute-warp constants: ALL 8 warps; warp w: gate q=w>>1, half h=w&1
    const int q  = wid >> 1;
    const int nh = wid & 1;
    const int ncol = q * 16 + nh * 8;     // Wsh row / Gsh col base (8 cols)

    // ldmatrix per-lane addresses (byte offsets into dynamic smem):
    const uint32_t aAddr1 = sb + (uint32_t)((64 * W_STR) + (lane & 15) * W_STR + ((lane >> 4) << 2)) * 4;
    const uint32_t aAddr2 = aAddr1 + (uint32_t)(16 * W_STR) * 4;
    // B x2: lanes 0-7 -> rows ncol+(lane&7) @k; lanes 8-15 -> same rows @k+4
    const uint32_t bAddr  = sb + (uint32_t)((ncol + (lane & 7)) * W_STR
                                            + (((lane >> 3) & 1) << 2)) * 4;

    // cell state: thread owns (b = tid>>3, j = (tid&7)*2 .. +1)
    const int cb = tid >> 3;
    const int cj = (tid & 7) * 2;
    float c_reg[2] = {0.f, 0.f};

    float c[2][4];      // 2 m-frags x 4 (N=8 frag)
    float pf[2][4];     // xp prefetch

    // prefetch xp for t=0 (warp's 8-col slice)
    {
        const float* xb = g_xp + ((size_t)0 * B_ + b0) * G4_ + q * 512 + j0 + nh * 8 + 2 * tig;
#pragma unroll
        for (int mf = 0; mf < 2; ++mf)
#pragma unroll
            for (int rs = 0; rs < 2; ++rs) {
                float2 v = *(const float2*)(xb + (size_t)(mf * 16 + g + rs * 8) * G4_);
                pf[mf][rs * 2 + 0] = v.x;
                pf[mf][rs * 2 + 1] = v.y;
            }
    }

    for (int t = 0; t < T_; ++t) {
#pragma unroll
        for (int mf = 0; mf < 2; ++mf)
#pragma unroll
            for (int i = 0; i < 4; ++i) c[mf][i] = pf[mf][i];

        if (t > 0) {
            // stage h_{t-1}: [32 b][512], L2-coherent loads (all 8 warps)
            {
                int row = tid >> 3;
                int s   = (tid & 7) * 4;
                const float* src = g_h[(t - 1) & 1] + (size_t)(b0 + row) * H_ + s;
                float* dst = Hsh + row * W_STR + s;
#pragma unroll
                for (int i = 0; i < 16; ++i) {
                    float4 v = __ldcg((const float4*)(src + i * 32));
                    *(float4*)(dst + i * 32) = v;
                }
            }
            __syncthreads();

            // mma over K=512: all 8 warps, 2 mma per k-step
#pragma unroll 4
            for (int kk = 0; kk < 64; ++kk) {
                const uint32_t koff = (uint32_t)kk * 32;   // 8 floats per k-step
                uint32_t af0[4], af1[4], bb[2];
                ldsm4(af0, aAddr1 + koff);
                ldsm4(af1, aAddr2 + koff);
                ldsm2(bb,  bAddr  + koff);
                mma1688(c[0], af0, bb);
                mma1688(c[1], af1, bb);
            }
        }

        // stage gates to SMEM (each warp: its 8-col slice)
#pragma unroll
        for (int mf = 0; mf < 2; ++mf)
#pragma unroll
            for (int rs = 0; rs < 2; ++rs) {
                float* gr = Gsh + (mf * 16 + g + rs * 8) * G_STR + ncol + 2 * tig;
                float2 v;
                v.x = c[mf][rs * 2 + 0];
                v.y = c[mf][rs * 2 + 1];
                *(float2*)gr = v;
            }
        __syncthreads();

        // prefetch xp for t+1 (independent of this step's cell)
        if (t + 1 < T_) {
            const float* xb = g_xp + ((size_t)(t + 1) * B_ + b0) * G4_ + q * 512 + j0 + nh * 8 + 2 * tig;
#pragma unroll
            for (int mf = 0; mf < 2; ++mf)
#pragma unroll
                for (int rs = 0; rs < 2; ++rs) {
                    float2 v = *(const float2*)(xb + (size_t)(mf * 16 + g + rs * 8) * G4_);
                    pf[mf][rs * 2 + 0] = v.x;
                    pf[mf][rs * 2 + 1] = v.y;
                }
        }

        // fused LSTM cell: 2 elements per thread, c in registers
        {
            const float* gr = Gsh + cb * G_STR;
            float h2[2];
#pragma unroll
            for (int p = 0; p < 2; ++p) {
                int j = cj + p;
                float gi = gr[0  + j];
                float gf = gr[16 + j];
                float gg = gr[32 + j];
                float go = gr[48 + j];
                float i_s = 1.f / (1.f + __expf(-gi));
                float f_s = 1.f / (1.f + __expf(-gf));
                float o_s = 1.f / (1.f + __expf(-go));
                float g_t = tanhf(gg);
                float cv  = f_s * c_reg[p] + i_s * g_t;
                c_reg[p]  = cv;
                h2[p]     = o_s * tanhf(cv);
            }
            float* op = out + ((size_t)t * B_ + b0 + cb) * H_ + j0 + cj;
            float2 ov; ov.x = h2[0]; ov.y = h2[1];
            *(float2*)op = ov;
            float* hp = g_h[t & 1] + (size_t)(b0 + cb) * H_ + j0 + cj;
            float2 hv; hv.x = tf32r(h2[0]); hv.y = tf32r(h2[1]);
            *(float2*)hp = hv;
        }

        grid_barrier_bt(t, bt);
    }
}

// =====================================================================
extern "C" void kernel_launch(void* const* d_in, const int* in_sizes, int n_in,
                              void* d_out, int out_size)
{
    const float* x   = (const float*)d_in[0];   // [B,T,D]
    const float* Wih = (const float*)d_in[1];   // [4H,D]
    const float* Whh = (const float*)d_in[2];   // [4H,H]
    const float* bih = (const float*)d_in[3];   // [4H]
    const float* bhh = (const float*)d_in[4];   // [4H]
    float* out = (float*)d_out;

    cudaFuncSetAttribute(xproj_mma,
                         cudaFuncAttributeMaxDynamicSharedMemorySize, XP_SMEM);
    xproj_mma<<<16384, 256, XP_SMEM>>>(x, Wih, bih, bhh);

    cudaFuncSetAttribute(lstm_rec_mma,
                         cudaFuncAttributeMaxDynamicSharedMemorySize, REC_SMEM);
    lstm_rec_mma<<<128, 256, REC_SMEM>>>(Whh, out);
}

// round 17
// speedup vs baseline: 1.0704x; 1.0704x over previous
#include <cuda_runtime.h>
#include <math.h>
#include <cstdint>

#define B_   128
#define T_   512
#define D_   256
#define H_   512
#define G4_  2048   // 4*H

// ---- static device scratch (no cudaMalloc allowed) ----
__device__ float g_xp[(size_t)T_ * B_ * G4_];   // [T*B, 4H] x-projections (+biases)
__device__ float g_h[2][B_ * H_];               // ping-pong hidden state (tf32-rounded)
__device__ unsigned g_cntB[128];                // 4 bt-group barrier counters, 128B apart
__device__ volatile unsigned g_genB[128];       // 4 bt-group barrier generations

// =====================================================================
// helpers
// =====================================================================
__device__ __forceinline__ float tf32r(float x) {
    float y; asm("cvt.rna.tf32.f32 %0, %1;" : "=f"(y) : "f"(x)); return y;
}
__device__ __forceinline__ uint32_t smem_u32(const void* p) {
    uint32_t a;
    asm("{ .reg .u64 t; cvta.to.shared.u64 t, %1; cvt.u32.u64 %0, t; }" : "=r"(a) : "l"(p));
    return a;
}
// ldmatrix x4: four 8x8 b16 tiles == one 16x8 tf32 A-frag or two 8x8 tf32 B-frags
__device__ __forceinline__ void ldsm4(uint32_t* r, uint32_t addr) {
    asm volatile("ldmatrix.sync.aligned.m8n8.x4.shared.b16 {%0,%1,%2,%3}, [%4];"
                 : "=r"(r[0]), "=r"(r[1]), "=r"(r[2]), "=r"(r[3]) : "r"(addr));
}
// mma.sync m16n8k8 tf32, fp32 accum
__device__ __forceinline__ void mma1688(float* c, const uint32_t* a, const uint32_t* b) {
    asm volatile(
        "mma.sync.aligned.m16n8k8.row.col.f32.tf32.tf32.f32 "
        "{%0,%1,%2,%3}, {%4,%5,%6,%7}, {%8,%9}, {%0,%1,%2,%3};"
        : "+f"(c[0]), "+f"(c[1]), "+f"(c[2]), "+f"(c[3])
        : "r"(a[0]), "r"(a[1]), "r"(a[2]), "r"(a[3]), "r"(b[0]), "r"(b[1]));
}
// 32-CTA bt-group barrier
__device__ __forceinline__ void grid_barrier_bt(int step, int bt)
{
    __syncthreads();
    if (threadIdx.x == 0) {
        unsigned next = (unsigned)((step + 1) & (T_ - 1));
        __threadfence();
        unsigned old = atomicAdd(&g_cntB[bt * 32], 1u);
        if (old == 31u) {
            g_cntB[bt * 32] = 0;
            __threadfence();
            g_genB[bt * 32] = next;
        } else {
            while (g_genB[bt * 32] != next) { }
        }
        __threadfence();
    }
    __syncthreads();
}

// =====================================================================
// Kernel 1: x_proj GEMM via tf32 mma + ldmatrix (round-13 exact)
// =====================================================================
#define XA_STR 68
#define XB_STR 68
#define XP_SMEM ((128 * XA_STR + 64 * XB_STR) * 4)

__global__ void __launch_bounds__(256, 1) xproj_mma(
    const float* __restrict__ x,     // [B*T, D]
    const float* __restrict__ Wih,   // [4H, D]
    const float* __restrict__ bih,
    const float* __restrict__ bhh)
{
    extern __shared__ float sm[];
    float* Ash = sm;                   // [128][68]
    float* Bsh = sm + 128 * XA_STR;    // [64][68]
    const uint32_t sb = smem_u32(sm);

    const int tid  = threadIdx.x;
    const int wid  = tid >> 5;
    const int lane = tid & 31;
    const int g    = lane >> 2;
    const int tig  = lane & 3;
    const int wm   = wid & 3;
    const int wcol = (wid >> 2) * 32;

    const int mt = blockIdx.x >> 5;
    const int nt = blockIdx.x & 31;
    const int m0 = mt * 128;
    const int n0 = nt * 64;

    const uint32_t aAddr1 = sb + (uint32_t)((wm * 32 + (lane & 15)) * XA_STR + ((lane >> 4) << 2)) * 4;
    const uint32_t aAddr2 = aAddr1 + (uint32_t)(16 * XA_STR) * 4;
    const uint32_t bBase  = sb + (uint32_t)(128 * XA_STR) * 4;
    const uint32_t bAddr1 = bBase + (uint32_t)((wcol + (lane & 7) + ((lane >> 4) << 3)) * XB_STR
                                               + (((lane >> 3) & 1) << 2)) * 4;
    const uint32_t bAddr2 = bAddr1 + (uint32_t)(16 * XB_STR) * 4;

    float c[2][4][4];
#pragma unroll
    for (int a = 0; a < 2; ++a)
#pragma unroll
        for (int b = 0; b < 4; ++b)
#pragma unroll
            for (int i = 0; i < 4; ++i) c[a][b][i] = 0.f;

    for (int kc = 0; kc < 4; ++kc) {
        const int k0 = kc * 64;
        __syncthreads();
        {
            int row = tid >> 1;
            int h   = (tid & 1) * 32;
            const float* src = x + (size_t)(m0 + row) * D_ + k0 + h;
            float* dst = Ash + row * XA_STR + h;
#pragma unroll
            for (int i = 0; i < 8; ++i) {
                float4 v = *(const float4*)(src + i * 4);
                v.x = tf32r(v.x); v.y = tf32r(v.y); v.z = tf32r(v.z); v.w = tf32r(v.w);
                *(float4*)(dst + i * 4) = v;
            }
        }
        {
            int n = tid >> 2;
            int h = (tid & 3) * 16;
            const float* src = Wih + (size_t)(n0 + n) * D_ + k0 + h;
            float* dst = Bsh + n * XB_STR + h;
#pragma unroll
            for (int i = 0; i < 4; ++i) {
                float4 v = *(const float4*)(src + i * 4);
                v.x = tf32r(v.x); v.y = tf32r(v.y); v.z = tf32r(v.z); v.w = tf32r(v.w);
                *(float4*)(dst + i * 4) = v;
            }
        }
        __syncthreads();

#pragma unroll 4
        for (int kk = 0; kk < 8; ++kk) {
            const uint32_t koff = (uint32_t)kk * 32;
            uint32_t af0[4], af1[4], bb01[4], bb23[4];
            ldsm4(af0,  aAddr1 + koff);
            ldsm4(af1,  aAddr2 + koff);
            ldsm4(bb01, bAddr1 + koff);
            ldsm4(bb23, bAddr2 + koff);
            mma1688(c[0][0], af0, bb01); mma1688(c[0][1], af0, bb01 + 2);
            mma1688(c[0][2], af0, bb23); mma1688(c[0][3], af0, bb23 + 2);
            mma1688(c[1][0], af1, bb01); mma1688(c[1][1], af1, bb01 + 2);
            mma1688(c[1][2], af1, bb23); mma1688(c[1][3], af1, bb23 + 2);
        }
    }

    float2 bias[4];
#pragma unroll
    for (int nf = 0; nf < 4; ++nf) {
        int col = n0 + wcol + nf * 8 + 2 * tig;
        bias[nf].x = bih[col] + bhh[col];
        bias[nf].y = bih[col + 1] + bhh[col + 1];
    }
#pragma unroll
    for (int mf = 0; mf < 2; ++mf) {
#pragma unroll
        for (int rs = 0; rs < 2; ++rs) {
            int grow = m0 + wm * 32 + mf * 16 + g + rs * 8;
            int b = grow >> 9;
            int t = grow & 511;
            float* orow = g_xp + ((size_t)t * B_ + b) * G4_ + n0 + wcol + 2 * tig;
#pragma unroll
            for (int nf = 0; nf < 4; ++nf) {
                float2 v;
                v.x = c[mf][nf][rs * 2 + 0] + bias[nf].x;
                v.y = c[mf][nf][rs * 2 + 1] + bias[nf].y;
                *(float2*)(orow + nf * 8) = v;
            }
        }
    }
}

// =====================================================================
// Kernel 2: persistent tf32 mma recurrence (round-12 hot loop,
//           gate-interleaved N packing -> cell fully in registers).
//   128 CTAs (4 bt x 32 jt) x 256 threads; warps 0-3 compute.
//   Wsh col packing within warp-block w (rows w*16+c):
//     gate = (c&1) + 2*(c>>3),  j = 4*w + ((c&7)>>1)
//   => after 2 mma/kk, thread (g,tig) of warp w holds ALL 4 gates for
//      elements (b in {g,g+8,g+16,g+24}, j = j0+4w+tig) in registers.
//   Deletes Gsh staging, the 2nd __syncthreads, and the cell SMEM reads.
// =====================================================================
#define W_STR 516           // Wsh/Hsh row stride (floats), pad 4
#define REC_SMEM ((96 * W_STR) * 4)

__global__ void __launch_bounds__(256, 1) lstm_rec_mma(
    const float* __restrict__ Whh,   // [4H, H]
    float* __restrict__ out)         // [T*B, H]
{
    extern __shared__ float sm[];
    float* Wsh = sm;                     // [64 n][516] gate-interleaved
    float* Hsh = sm + 64 * W_STR;        // [32 b][516]
    const uint32_t sb = smem_u32(sm);

    const int tid  = threadIdx.x;
    const int wid  = tid >> 5;
    const int lane = tid & 31;
    const int g    = lane >> 2;
    const int tig  = lane & 3;

    const int bt = blockIdx.x >> 5;
    const int jt = blockIdx.x & 31;
    const int b0 = bt * 32;
    const int j0 = jt * 16;

    // ---- one-time: W_hh slice -> SMEM, gate-interleaved cols (tf32-rna) ----
    {
        int n  = tid >> 2;               // 0..63
        int kq = (tid & 3) * 128;
        int wb = n >> 4;                 // warp block 0..3
        int cc = n & 15;
        int gate = (cc & 1) + ((cc >> 3) << 1);
        int jl   = wb * 4 + ((cc & 7) >> 1);
        const float* wr = Whh + (size_t)(gate * H_ + j0 + jl) * H_ + kq;
        float* dst = Wsh + n * W_STR + kq;
#pragma unroll 8
        for (int i = 0; i < 128; i += 4) {
            float4 v = *(const float4*)(wr + i);
            v.x = tf32r(v.x); v.y = tf32r(v.y); v.z = tf32r(v.z); v.w = tf32r(v.w);
            *(float4*)(dst + i) = v;
        }
    }
    __syncthreads();

    // compute-warp constants (warps 0-3)
    const int ncol = wid * 16;            // B rows for this warp
    const int jg   = j0 + wid * 4 + tig;  // this thread's hidden index

    // ldmatrix per-lane addresses (byte offsets into dynamic smem):
    const uint32_t aAddr1 = sb + (uint32_t)((64 * W_STR) + (lane & 15) * W_STR + ((lane >> 4) << 2)) * 4;
    const uint32_t aAddr2 = aAddr1 + (uint32_t)(16 * W_STR) * 4;
    const uint32_t bAddr  = sb + (uint32_t)((ncol + (lane & 7) + ((lane >> 4) << 3)) * W_STR
                                            + (((lane >> 3) & 1) << 2)) * 4;

    // cell state: 4 elements per compute thread (rows g, g+8, g+16, g+24)
    float c_state[4] = {0.f, 0.f, 0.f, 0.f};

    float c[2][2][4];
    float pf[4][4];     // xp prefetch: [e = row-slot][gate]

    // prefetch xp for t=0
    if (wid < 4) {
#pragma unroll
        for (int e = 0; e < 4; ++e) {
            int row = g + (e & 1) * 8 + (e >> 1) * 16;
            const float* p = g_xp + ((size_t)0 * B_ + b0 + row) * G4_ + jg;
#pragma unroll
            for (int qd = 0; qd < 4; ++qd) pf[e][qd] = __ldg(p + qd * 512);
        }
    }

    for (int t = 0; t < T_; ++t) {
        // acc init from xp: acc[mf][0][hi*2+0]=gate_i, [0][hi*2+1]=gate_f,
        //                   [1][hi*2+0]=gate_g, [1][hi*2+1]=gate_o  (e = mf*2+hi)
        if (wid < 4) {
#pragma unroll
            for (int mf = 0; mf < 2; ++mf)
#pragma unroll
                for (int hi = 0; hi < 2; ++hi) {
                    int e = mf * 2 + hi;
                    c[mf][0][hi * 2 + 0] = pf[e][0];
                    c[mf][0][hi * 2 + 1] = pf[e][1];
                    c[mf][1][hi * 2 + 0] = pf[e][2];
                    c[mf][1][hi * 2 + 1] = pf[e][3];
                }
        }

        if (t > 0) {
            // stage h_{t-1}: [32 b][512], L2-coherent loads (all 8 warps)
            {
                int row = tid >> 3;
                int s   = (tid & 7) * 4;
                const float* src = g_h[(t - 1) & 1] + (size_t)(b0 + row) * H_ + s;
                float* dst = Hsh + row * W_STR + s;
#pragma unroll
                for (int i = 0; i < 16; ++i) {
                    float4 v = __ldcg((const float4*)(src + i * 32));
                    *(float4*)(dst + i * 32) = v;
                }
            }
            __syncthreads();

            if (wid < 4) {
#pragma unroll 4
                for (int kk = 0; kk < 64; ++kk) {
                    const uint32_t koff = (uint32_t)kk * 32;   // 8 floats per k-step
                    uint32_t af0[4], af1[4], bb[4];
                    ldsm4(af0, aAddr1 + koff);
                    ldsm4(af1, aAddr2 + koff);
                    ldsm4(bb,  bAddr  + koff);
                    mma1688(c[0][0], af0, bb);     mma1688(c[0][1], af0, bb + 2);
                    mma1688(c[1][0], af1, bb);     mma1688(c[1][1], af1, bb + 2);
                }
            }
        } else {
            __syncthreads();   // keep warps converged at one sync per phase
        }

        if (wid < 4) {
            // prefetch xp for t+1 (in flight during cell math)
            if (t + 1 < T_) {
#pragma unroll
                for (int e = 0; e < 4; ++e) {
                    int row = g + (e & 1) * 8 + (e >> 1) * 16;
                    const float* p = g_xp + ((size_t)(t + 1) * B_ + b0 + row) * G4_ + jg;
#pragma unroll
                    for (int qd = 0; qd < 4; ++qd) pf[e][qd] = __ldg(p + qd * 512);
                }
            }

            // fused LSTM cell: fully in registers, 4 elements per thread
            float* hb = g_h[t & 1];
#pragma unroll
            for (int mf = 0; mf < 2; ++mf)
#pragma unroll
                for (int hi = 0; hi < 2; ++hi) {
                    int e   = mf * 2 + hi;
                    int row = g + hi * 8 + mf * 16;
                    float gi = c[mf][0][hi * 2 + 0];
                    float gf = c[mf][0][hi * 2 + 1];
                    float gg = c[mf][1][hi * 2 + 0];
                    float go = c[mf][1][hi * 2 + 1];
                    float i_s = 1.f / (1.f + __expf(-gi));
                    float f_s = 1.f / (1.f + __expf(-gf));
                    float g_t = tanhf(gg);
                    float o_s = 1.f / (1.f + __expf(-go));
                    float cv  = f_s * c_state[e] + i_s * g_t;
                    c_state[e] = cv;
                    float hv  = o_s * tanhf(cv);
                    out[((size_t)t * B_ + b0 + row) * H_ + jg] = hv;
                    hb[(size_t)(b0 + row) * H_ + jg] = tf32r(hv);
                }
        }

        grid_barrier_bt(t, bt);
    }
}

// =====================================================================
extern "C" void kernel_launch(void* const* d_in, const int* in_sizes, int n_in,
                              void* d_out, int out_size)
{
    const float* x   = (const float*)d_in[0];   // [B,T,D]
    const float* Wih = (const float*)d_in[1];   // [4H,D]
    const float* Whh = (const float*)d_in[2];   // [4H,H]
    const float* bih = (const float*)d_in[3];   // [4H]
    const float* bhh = (const float*)d_in[4];   // [4H]
    float* out = (float*)d_out;

    cudaFuncSetAttribute(xproj_mma,
                         cudaFuncAttributeMaxDynamicSharedMemorySize, XP_SMEM);
    xproj_mma<<<16384, 256, XP_SMEM>>>(x, Wih, bih, bhh);

    cudaFuncSetAttribute(lstm_rec_mma,
                         cudaFuncAttributeMaxDynamicSharedMemorySize, REC_SMEM);
    lstm_rec_mma<<<128, 256, REC_SMEM>>>(Whh, out);
}